// round 2
// baseline (speedup 1.0000x reference)
#include <cuda_runtime.h>

#define TT 2048
#define BB 32
#define HH 512

// Scratch (allocation-free: __device__ globals)
__device__ float g_alphaT[TT * BB];   // alphas transposed [t][b]
__device__ float g_xT[TT * BB];       // integ-after-add (the "fires" value), [t][b]
__device__ int   g_fireT[TT];         // fire timestep list for batch 0
__device__ int   g_nF;                // number of fires, batch 0
__device__ int   g_lastFire[BB];      // last fire index per batch (-1 if none)

// ---------------------------------------------------------------------------
// Kernel 1: transpose alphas [B][T] -> [T][B] so the scan warp loads coalesced
// ---------------------------------------------------------------------------
__global__ void k_transpose(const float* __restrict__ alphas) {
    __shared__ float s[32][33];
    int tx = threadIdx.x, ty = threadIdx.y;
    int tbase = blockIdx.x * 32;
    // ty = batch, tx = t within tile : coalesced read over t
    s[ty][tx] = alphas[ty * TT + tbase + tx];
    __syncthreads();
    // tx = batch (coalesced write), ty = t within tile
    g_alphaT[(tbase + ty) * BB + tx] = s[tx][ty];
}

// ---------------------------------------------------------------------------
// Kernel 2: single-warp scan, lane = batch. Bit-exact f32 sequential.
// Chain/step: FADD(x=integ+a) -> FSETP(x>=1) -> FSEL = 12 cycles.
// ---------------------------------------------------------------------------
__global__ void k_scan(const float* __restrict__ integrate,
                       float* __restrict__ out_integ) {
    int lane = threadIdx.x;
    float integ = integrate[lane];
    int lf = -1;
    int cnt = 0;

    const int U = 32;  // prefetch depth: 32 * ~12.5 cyc = 400 cyc shadow > L2 lat
    float abuf[U];
#pragma unroll
    for (int u = 0; u < U; u++) abuf[u] = g_alphaT[u * BB + lane];

    for (int blk = 0; blk < TT / U; blk++) {
        float anext[U];
        if (blk + 1 < TT / U) {
#pragma unroll
            for (int u = 0; u < U; u++)
                anext[u] = g_alphaT[((blk + 1) * U + u) * BB + lane];
        } else {
#pragma unroll
            for (int u = 0; u < U; u++) anext[u] = 0.0f;
        }
#pragma unroll
        for (int u = 0; u < U; u++) {
            int t = blk * U + u;
            float a = abuf[u];
            float x = integ + a;           // fl(integ + alpha)  == fires value
            g_xT[t * BB + lane] = x;       // coalesced STG (t-major)
            bool p = (x >= 1.0f);          // fire
            float y = x - 1.0f;            // exact for x in [1,2)
            integ = p ? y : x;
            lf = p ? t : lf;
            if (p && lane == 0) {          // batch-0 fire index compaction
                g_fireT[cnt] = t;          // predicated; hides in chain stalls
                cnt++;
            }
        }
#pragma unroll
        for (int u = 0; u < U; u++) abuf[u] = anext[u];
    }

    g_lastFire[lane] = lf;
    out_integ[lane] = integ;               // integrate_new output
    if (lane == 0) g_nF = cnt;
}

// Reconstruct carry integ from stored x (bit-exact: x-1 is exact on [1,2))
__device__ __forceinline__ float integ_after(float x) {
    return (x >= 1.0f) ? (x - 1.0f) : x;
}

// ---------------------------------------------------------------------------
// Kernel 3: blocks 0..2047 -> frame_sel rows; blocks 2048..2079 -> frame_new.
// 128 threads, float4 over H=512.
// ---------------------------------------------------------------------------
__global__ void k_frames(const float* __restrict__ hidden,
                         const float* __restrict__ alphas,
                         const float* __restrict__ integrate,
                         const float* __restrict__ frame,
                         float* __restrict__ out) {
    int i   = blockIdx.x;
    int tid = threadIdx.x;  // 0..127

    if (i < TT) {
        const float4* H0 = (const float4*)hidden;  // batch 0: [t][128]
        float4* orow = (float4*)out + (size_t)i * 128 + tid;
        int nF = g_nF;

        if (i >= nF) {
            // fill rows: frames[0][0] = frame_init + cur_0 * h_0
            float x0 = g_xT[0];
            float cur0 = (x0 >= 1.0f) ? (1.0f - integrate[0]) : alphas[0];
            float4 h = H0[tid];
            float4 f = ((const float4*)frame)[tid];
            float4 r;
            r.x = f.x + cur0 * h.x; r.y = f.y + cur0 * h.y;
            r.z = f.z + cur0 * h.z; r.w = f.w + cur0 * h.w;
            *orow = r;
        } else {
            int tE = g_fireT[i];
            float4 acc;
            int tstart;
            if (i == 0) {
                acc = ((const float4*)frame)[tid];  // initial frame carried in
                tstart = 0;
            } else {
                // lead term from previous fire: rem_{tp} * h_{tp}
                int tp = g_fireT[i - 1];
                float alpha_p = alphas[tp];
                float integ_pm1 = (tp == 0) ? integrate[0]
                                            : integ_after(g_xT[(tp - 1) * BB]);
                float cur_p = 1.0f - integ_pm1;     // dist_completion at tp
                float rem = alpha_p - cur_p;
                float4 h = H0[(size_t)tp * 128 + tid];
                acc.x = rem * h.x; acc.y = rem * h.y;
                acc.z = rem * h.z; acc.w = rem * h.w;
                tstart = tp + 1;
            }
            // interior steps (non-fire): cur = alpha
            for (int t = tstart; t < tE; t++) {
                float w = alphas[t];
                float4 h = H0[(size_t)t * 128 + tid];
                acc.x += w * h.x; acc.y += w * h.y;
                acc.z += w * h.z; acc.w += w * h.w;
            }
            // closing fire step: cur = 1 - integ_{tE-1}
            float integ_prev = (tE == 0) ? integrate[0]
                                         : integ_after(g_xT[(tE - 1) * BB]);
            float w = 1.0f - integ_prev;
            float4 h = H0[(size_t)tE * 128 + tid];
            acc.x += w * h.x; acc.y += w * h.y;
            acc.z += w * h.z; acc.w += w * h.w;
            *orow = acc;
        }
    } else {
        // frame_new for batch b: tail segment after last fire
        int b = i - TT;
        const float4* Hb = (const float4*)(hidden + (size_t)b * TT * HH);
        int lf = g_lastFire[b];
        float4 acc;
        int tstart;
        if (lf < 0) {
            acc = ((const float4*)frame)[(size_t)b * 128 + tid];
            tstart = 0;
        } else {
            float alpha_p = alphas[(size_t)b * TT + lf];
            float integ_pm1 = (lf == 0) ? integrate[b]
                                        : integ_after(g_xT[(lf - 1) * BB + b]);
            float cur = 1.0f - integ_pm1;
            float rem = alpha_p - cur;
            float4 h = Hb[(size_t)lf * 128 + tid];
            acc.x = rem * h.x; acc.y = rem * h.y;
            acc.z = rem * h.z; acc.w = rem * h.w;
            tstart = lf + 1;
        }
        for (int t = tstart; t < TT; t++) {
            float w = alphas[(size_t)b * TT + t];
            float4 h = Hb[(size_t)t * 128 + tid];
            acc.x += w * h.x; acc.y += w * h.y;
            acc.z += w * h.z; acc.w += w * h.w;
        }
        // out layout: [frame_sel T*H][integrate_new B][frame_new B*H]
        float4* od = (float4*)(out + (size_t)TT * HH + BB) + (size_t)b * 128 + tid;
        *od = acc;
    }
}

extern "C" void kernel_launch(void* const* d_in, const int* in_sizes, int n_in,
                              void* d_out, int out_size) {
    const float* hidden    = (const float*)d_in[0];
    const float* alphas    = (const float*)d_in[1];
    const float* integrate = (const float*)d_in[2];
    const float* frame     = (const float*)d_in[3];
    float* out = (float*)d_out;

    dim3 tb(32, 32);
    k_transpose<<<TT / 32, tb>>>(alphas);
    k_scan<<<1, 32>>>(integrate, out + (size_t)TT * HH);
    k_frames<<<TT + BB, 128>>>(hidden, alphas, integrate, frame, out);
}

// round 3
// speedup vs baseline: 1.3204x; 1.3204x over previous
#include <cuda_runtime.h>

#define TT 2048
#define BB 32
#define HH 512

// Scratch (allocation-free: __device__ globals)
__device__ uint2 g_fire[TT];       // (t, bits(dist_completion)) per batch-0 fire
__device__ int   g_nF;             // number of fires, batch 0
__device__ int   g_lastFire[BB];   // last fire index per batch (-1 if none)
__device__ float g_lastDist[BB];   // dist_completion at that fire

// ---------------------------------------------------------------------------
// Kernel 1: single-warp scan, lane = batch. Bit-exact f32 sequential.
// Chain/step: FADD(x=integ+a) -> FSETP(x>=1) -> FSEL = 12 cycles.
// All bookkeeping (dist, lf, ldist, fire records) is off the chain; fire
// records buffer in shared (cheap STS) and dump once at the end.
// ---------------------------------------------------------------------------
__global__ void k_scan(const float* __restrict__ alphas,
                       const float* __restrict__ integrate,
                       float* __restrict__ out_integ) {
    __shared__ uint2 s_fire[TT];
    int lane = threadIdx.x;
    const float4* A = (const float4*)(alphas + lane * TT);  // lane's own batch row
    float integ = integrate[lane];
    int   lf = -1;
    float ldist = 0.0f;
    int   cnt = 0;

    float4 buf[8];
#pragma unroll
    for (int j = 0; j < 8; j++) buf[j] = A[j];

    for (int blk = 0; blk < TT / 32; blk++) {
        float4 nxt[8];
        if (blk + 1 < TT / 32) {
#pragma unroll
            for (int j = 0; j < 8; j++) nxt[j] = A[(blk + 1) * 8 + j];
        }
        float av[32];
#pragma unroll
        for (int j = 0; j < 8; j++) {
            av[4 * j + 0] = buf[j].x; av[4 * j + 1] = buf[j].y;
            av[4 * j + 2] = buf[j].z; av[4 * j + 3] = buf[j].w;
        }
#pragma unroll
        for (int u = 0; u < 32; u++) {
            int t = blk * 32 + u;
            float a = av[u];
            float x = integ + a;            // fl(integ + alpha) == "fires" value
            bool  p = (x >= 1.0f);          // fire decision
            float y = x - 1.0f;             // exact for x in [1,2) (Sterbenz)
            float dist = 1.0f - integ;      // dist_completion (off-chain)
            integ = p ? y : x;              // 12-cyc carried chain
            if (p) { lf = t; ldist = dist; }
            if (p && lane == 0) {           // batch-0 fire record (predicated STS)
                s_fire[cnt] = make_uint2((unsigned)t, __float_as_uint(dist));
                cnt++;
            }
        }
        if (blk + 1 < TT / 32) {
#pragma unroll
            for (int j = 0; j < 8; j++) buf[j] = nxt[j];
        }
    }

    g_lastFire[lane] = lf;
    g_lastDist[lane] = ldist;
    out_integ[lane]  = integ;               // integrate_new output

    int n = __shfl_sync(0xffffffffu, cnt, 0);
    if (lane == 0) g_nF = n;
    for (int i = lane; i < n; i += 32) g_fire[i] = s_fire[i];  // coalesced dump
}

// ---------------------------------------------------------------------------
// Kernel 2: blocks 0..2047 -> frame_sel rows; blocks 2048..2079 -> frame_new.
// 128 threads, float4 over H=512. Segment sums are ~2 steps each.
// ---------------------------------------------------------------------------
__global__ void k_frames(const float* __restrict__ hidden,
                         const float* __restrict__ alphas,
                         const float* __restrict__ integrate,
                         const float* __restrict__ frame,
                         float* __restrict__ out) {
    int i   = blockIdx.x;
    int tid = threadIdx.x;  // 0..127

    if (i < TT) {
        const float4* H0 = (const float4*)hidden;  // batch 0: [t][128]
        float4* orow = (float4*)out + (size_t)i * 128 + tid;
        int nF = g_nF;

        if (i >= nF) {
            // fill rows replicate frames[0][0] = frame_init + cur_0 * h_0
            float cur0;
            if (nF > 0 && g_fire[0].x == 0u)
                cur0 = __uint_as_float(g_fire[0].y);   // fired at t=0: dist
            else
                cur0 = alphas[0];                      // no fire at t=0: alpha
            float4 h = H0[tid];
            float4 f = ((const float4*)frame)[tid];
            float4 r;
            r.x = f.x + cur0 * h.x; r.y = f.y + cur0 * h.y;
            r.z = f.z + cur0 * h.z; r.w = f.w + cur0 * h.w;
            *orow = r;
        } else {
            uint2 fe = g_fire[i];
            int   tE = (int)fe.x;
            float wE = __uint_as_float(fe.y);          // cur at closing fire
            float4 acc;
            int tstart;
            if (i == 0) {
                acc = ((const float4*)frame)[tid];     // initial frame carried in
                tstart = 0;
            } else {
                // lead term from previous fire: rem_{tp} * h_{tp}
                uint2 fp = g_fire[i - 1];
                int   tp = (int)fp.x;
                float cur_p = __uint_as_float(fp.y);
                float rem = alphas[tp] - cur_p;        // bitwise same as scan's rem
                float4 h = H0[(size_t)tp * 128 + tid];
                acc.x = rem * h.x; acc.y = rem * h.y;
                acc.z = rem * h.z; acc.w = rem * h.w;
                tstart = tp + 1;
            }
            // interior steps (non-fire): cur = alpha
            for (int t = tstart; t < tE; t++) {
                float w = alphas[t];
                float4 h = H0[(size_t)t * 128 + tid];
                acc.x += w * h.x; acc.y += w * h.y;
                acc.z += w * h.z; acc.w += w * h.w;
            }
            // closing fire step: cur = dist_completion
            float4 h = H0[(size_t)tE * 128 + tid];
            acc.x += wE * h.x; acc.y += wE * h.y;
            acc.z += wE * h.z; acc.w += wE * h.w;
            *orow = acc;
        }
    } else {
        // frame_new for batch b: tail segment after last fire
        int b = i - TT;
        const float4* Hb = (const float4*)(hidden + (size_t)b * TT * HH);
        int lf = g_lastFire[b];
        float4 acc;
        int tstart;
        if (lf < 0) {
            acc = ((const float4*)frame)[(size_t)b * 128 + tid];
            tstart = 0;
        } else {
            float dist = g_lastDist[b];
            float rem = alphas[(size_t)b * TT + lf] - dist;
            float4 h = Hb[(size_t)lf * 128 + tid];
            acc.x = rem * h.x; acc.y = rem * h.y;
            acc.z = rem * h.z; acc.w = rem * h.w;
            tstart = lf + 1;
        }
        for (int t = tstart; t < TT; t++) {
            float w = alphas[(size_t)b * TT + t];
            float4 h = Hb[(size_t)t * 128 + tid];
            acc.x += w * h.x; acc.y += w * h.y;
            acc.z += w * h.z; acc.w += w * h.w;
        }
        // out layout: [frame_sel T*H][integrate_new B][frame_new B*H]
        float4* od = (float4*)(out + (size_t)TT * HH + BB) + (size_t)b * 128 + tid;
        *od = acc;
    }
}

extern "C" void kernel_launch(void* const* d_in, const int* in_sizes, int n_in,
                              void* d_out, int out_size) {
    const float* hidden    = (const float*)d_in[0];
    const float* alphas    = (const float*)d_in[1];
    const float* integrate = (const float*)d_in[2];
    const float* frame     = (const float*)d_in[3];
    float* out = (float*)d_out;

    k_scan<<<1, 32>>>(alphas, integrate, out + (size_t)TT * HH);
    k_frames<<<TT + BB, 128>>>(hidden, alphas, integrate, frame, out);
}

// round 4
// speedup vs baseline: 1.4510x; 1.0988x over previous
#include <cuda_runtime.h>

#define TT 2048
#define BB 32
#define HH 512

// Scratch (allocation-free: __device__ globals)
__device__ uint2 g_fire[TT];       // (t, bits(dist_completion)) per batch-0 fire
__device__ int   g_nF;             // number of fires, batch 0
__device__ int   g_lastFire[BB];   // last fire index per batch (-1 if none)
__device__ float g_lastDist[BB];   // dist_completion at that fire

// Carry reconstruction: x-1 exact for x in [1,2) (Sterbenz)
__device__ __forceinline__ float integ_after(float x) {
    return (x >= 1.0f) ? (x - 1.0f) : x;
}

// ---------------------------------------------------------------------------
// Kernel 1: single-warp scan, lane = batch. Bit-exact f32 sequential.
// Chain/step: FADD -> FSETP -> FSEL = 12 cyc. Inner loop is fully branchless:
// no if{} (ptxas would emit BSSY/BSYNC per step). Lane 0 records x_t to shared
// unconditionally; other lanes hit a dummy region (same-address collapse).
// Fire compaction happens once at the end via ballot.
// ---------------------------------------------------------------------------
__global__ void k_scan(const float* __restrict__ alphas,
                       const float* __restrict__ integrate,
                       float* __restrict__ out_integ) {
    __shared__ float s_x[TT];
    __shared__ float s_dummy[TT + 2];
    int lane = threadIdx.x;
    const float4* A = (const float4*)(alphas + lane * TT);  // lane's batch row
    float integ0 = integrate[lane];
    float integ  = integ0;
    int   lf  = -1;
    float lip = 0.0f;                     // integ (pre-update) at last fire
    float* sp = (lane == 0) ? s_x : (s_dummy + 1);  // +1: distinct bank vs s_x

    float4 buf[8], nxt[8];
#pragma unroll
    for (int j = 0; j < 8; j++) buf[j] = A[j];

#define GETA(B, u) ((u & 3) == 0 ? B[(u) >> 2].x : \
                    (u & 3) == 1 ? B[(u) >> 2].y : \
                    (u & 3) == 2 ? B[(u) >> 2].z : B[(u) >> 2].w)

#define BODY32(B, TBASE) do {                                   \
    float* spt = sp + (TBASE);                                  \
    _Pragma("unroll")                                           \
    for (int u = 0; u < 32; u++) {                              \
        float a = GETA(B, u);                                   \
        float x = integ + a;        /* fl(integ+alpha)       */ \
        bool  p = (x >= 1.0f);      /* fire                  */ \
        float y = x - 1.0f;         /* exact on [1,2)        */ \
        spt[u] = x;                 /* STS [R+imm], no branch*/ \
        float iold = integ;                                     \
        integ = p ? y : x;          /* 12-cyc carried chain  */ \
        lf  = p ? ((TBASE) + u) : lf;                           \
        lip = p ? iold : lip;                                   \
    } } while (0)

    for (int b2 = 0; b2 < TT / 64; b2++) {
#pragma unroll
        for (int j = 0; j < 8; j++) nxt[j] = A[b2 * 16 + 8 + j];
        BODY32(buf, b2 * 64);
        if (b2 + 1 < TT / 64) {
#pragma unroll
            for (int j = 0; j < 8; j++) buf[j] = A[(b2 + 1) * 16 + j];
        }
        BODY32(nxt, b2 * 64 + 32);
    }

    g_lastFire[lane] = lf;
    g_lastDist[lane] = 1.0f - lip;      // same bits as in-scan 1-integ at fire
    out_integ[lane]  = integ;           // integrate_new output

    __syncwarp();
    // Ballot-based compaction of batch-0 fires (64 iterations)
    float i0 = __shfl_sync(0xffffffffu, integ0, 0);
    int cnt = 0;
    for (int base = 0; base < TT; base += 32) {
        float x = s_x[base + lane];
        bool  f = (x >= 1.0f);
        unsigned m = __ballot_sync(0xffffffffu, f);
        if (f) {
            int pos = cnt + __popc(m & ((1u << lane) - 1u));
            float xprev = (base + lane == 0) ? i0 : integ_after(s_x[base + lane - 1]);
            float dist  = 1.0f - xprev;           // dist_completion at this fire
            g_fire[pos] = make_uint2((unsigned)(base + lane), __float_as_uint(dist));
        }
        cnt += __popc(m);
    }
    if (lane == 0) g_nF = cnt;
}

// ---------------------------------------------------------------------------
// Kernel 2: blocks 0..2047 -> frame_sel rows; blocks 2048..2079 -> frame_new.
// 128 threads, float4 over H=512. Segment sums are ~2 steps each.
// ---------------------------------------------------------------------------
__global__ void k_frames(const float* __restrict__ hidden,
                         const float* __restrict__ alphas,
                         const float* __restrict__ integrate,
                         const float* __restrict__ frame,
                         float* __restrict__ out) {
    int i   = blockIdx.x;
    int tid = threadIdx.x;  // 0..127

    if (i < TT) {
        const float4* H0 = (const float4*)hidden;  // batch 0: [t][128]
        float4* orow = (float4*)out + (size_t)i * 128 + tid;
        int nF = g_nF;

        if (i >= nF) {
            // fill rows replicate frames[0][0] = frame_init + cur_0 * h_0
            float cur0;
            if (nF > 0 && g_fire[0].x == 0u)
                cur0 = __uint_as_float(g_fire[0].y);   // fired at t=0: dist
            else
                cur0 = alphas[0];                      // no fire at t=0: alpha
            float4 h = H0[tid];
            float4 f = ((const float4*)frame)[tid];
            float4 r;
            r.x = f.x + cur0 * h.x; r.y = f.y + cur0 * h.y;
            r.z = f.z + cur0 * h.z; r.w = f.w + cur0 * h.w;
            *orow = r;
        } else {
            uint2 fe = g_fire[i];
            int   tE = (int)fe.x;
            float wE = __uint_as_float(fe.y);          // cur at closing fire
            float4 acc;
            int tstart;
            if (i == 0) {
                acc = ((const float4*)frame)[tid];     // initial frame carried in
                tstart = 0;
            } else {
                // lead term from previous fire: rem_{tp} * h_{tp}
                uint2 fp = g_fire[i - 1];
                int   tp = (int)fp.x;
                float cur_p = __uint_as_float(fp.y);
                float rem = alphas[tp] - cur_p;        // bitwise same as scan's rem
                float4 h = H0[(size_t)tp * 128 + tid];
                acc.x = rem * h.x; acc.y = rem * h.y;
                acc.z = rem * h.z; acc.w = rem * h.w;
                tstart = tp + 1;
            }
            // interior steps (non-fire): cur = alpha
            for (int t = tstart; t < tE; t++) {
                float w = alphas[t];
                float4 h = H0[(size_t)t * 128 + tid];
                acc.x += w * h.x; acc.y += w * h.y;
                acc.z += w * h.z; acc.w += w * h.w;
            }
            // closing fire step: cur = dist_completion
            float4 h = H0[(size_t)tE * 128 + tid];
            acc.x += wE * h.x; acc.y += wE * h.y;
            acc.z += wE * h.z; acc.w += wE * h.w;
            *orow = acc;
        }
    } else {
        // frame_new for batch b: tail segment after last fire
        int b = i - TT;
        const float4* Hb = (const float4*)(hidden + (size_t)b * TT * HH);
        int lf = g_lastFire[b];
        float4 acc;
        int tstart;
        if (lf < 0) {
            acc = ((const float4*)frame)[(size_t)b * 128 + tid];
            tstart = 0;
        } else {
            float dist = g_lastDist[b];
            float rem = alphas[(size_t)b * TT + lf] - dist;
            float4 h = Hb[(size_t)lf * 128 + tid];
            acc.x = rem * h.x; acc.y = rem * h.y;
            acc.z = rem * h.z; acc.w = rem * h.w;
            tstart = lf + 1;
        }
        for (int t = tstart; t < TT; t++) {
            float w = alphas[(size_t)b * TT + t];
            float4 h = Hb[(size_t)t * 128 + tid];
            acc.x += w * h.x; acc.y += w * h.y;
            acc.z += w * h.z; acc.w += w * h.w;
        }
        // out layout: [frame_sel T*H][integrate_new B][frame_new B*H]
        float4* od = (float4*)(out + (size_t)TT * HH + BB) + (size_t)b * 128 + tid;
        *od = acc;
    }
}

extern "C" void kernel_launch(void* const* d_in, const int* in_sizes, int n_in,
                              void* d_out, int out_size) {
    const float* hidden    = (const float*)d_in[0];
    const float* alphas    = (const float*)d_in[1];
    const float* integrate = (const float*)d_in[2];
    const float* frame     = (const float*)d_in[3];
    float* out = (float*)d_out;

    k_scan<<<1, 32>>>(alphas, integrate, out + (size_t)TT * HH);
    k_frames<<<TT + BB, 128>>>(hidden, alphas, integrate, frame, out);
}